// round 17
// baseline (speedup 1.0000x reference)
#include <cuda_runtime.h>
#include <cuda_fp16.h>
#include <math.h>
#include <stdint.h>

#define SEQ    2048
#define NQKV   6144
#define HID    2048

typedef unsigned long long u64;
typedef unsigned int u32;

// ------------------------- scratch (device globals) -------------------------
__device__ __half g_qh[(size_t)32 * SEQ * 128];       // Q single (pre-scaled) [bh][s][d]
__device__ __half g_kh[(size_t)32 * SEQ * 128];       // K single
__device__ __half g_vh[(size_t)32 * SEQ * 128];       // V single
__device__ __half g_ah[(size_t)4096 * 2048];          // A single [M][K] (activations)
__device__ __half g_bh[(size_t)6144 * 2048];          // B^T single [N][K] (weights)

// ------------------------- async / mma helpers (base PTX only) ---------------
__device__ __forceinline__ void cpa16(u32 dst, const void* src) {
    asm volatile("cp.async.cg.shared.global [%0], [%1], 16;" :: "r"(dst), "l"(src));
}
__device__ __forceinline__ void ldsm4(u32 r[4], u32 addr) {
    asm volatile("ldmatrix.sync.aligned.m8n8.x4.shared.b16 {%0,%1,%2,%3}, [%4];"
                 : "=r"(r[0]), "=r"(r[1]), "=r"(r[2]), "=r"(r[3]) : "r"(addr));
}
__device__ __forceinline__ void ldsm4t(u32 r[4], u32 addr) {
    asm volatile("ldmatrix.sync.aligned.m8n8.x4.trans.shared.b16 {%0,%1,%2,%3}, [%4];"
                 : "=r"(r[0]), "=r"(r[1]), "=r"(r[2]), "=r"(r[3]) : "r"(addr));
}
__device__ __forceinline__ void mma_f16(float c[4], const u32 a[4], const u32 b[2]) {
    asm volatile("mma.sync.aligned.m16n8k16.row.col.f32.f16.f16.f32 "
                 "{%0,%1,%2,%3}, {%4,%5,%6,%7}, {%8,%9}, {%0,%1,%2,%3};"
                 : "+f"(c[0]), "+f"(c[1]), "+f"(c[2]), "+f"(c[3])
                 : "r"(a[0]), "r"(a[1]), "r"(a[2]), "r"(a[3]), "r"(b[0]), "r"(b[1]));
}

// fast exp on the FMA pipe (rel err ~2.4e-6)
__device__ __forceinline__ float fexp(float x) {
    float t = fmaxf(x, -80.f) * 1.4426950408889634f;
    float z = t + 12582912.f;
    int e = __float_as_int(z) - 0x4B400000;
    float f = t - (z - 12582912.f);
    float g = f * 0.6931471805599453f;
    float r = fmaf(g, 0.0083333333f, 0.0416666667f);
    r = fmaf(g, r, 0.16666667f);
    r = fmaf(g, r, 0.5f);
    r = fmaf(g, r, 1.0f);
    r = fmaf(g, r, 1.0f);
    return r * __int_as_float((e + 127) << 23);
}

// ---------------------------------------------------------------------------
// fp32 -> fp16 convert (row-major activations)
// ---------------------------------------------------------------------------
__global__ void conv_rm(const float4* __restrict__ x, __half* __restrict__ hi, int n4)
{
    int i = blockIdx.x * 256 + threadIdx.x;
    if (i >= n4) return;
    float4 v = x[i];
    __half2 a = __floats2half2_rn(v.x, v.y);
    __half2 b = __floats2half2_rn(v.z, v.w);
    *(uint2*)(hi + 4 * (size_t)i) = make_uint2(*(u32*)&a, *(u32*)&b);
}

// W [K][N] row-major -> single fp16 [N][K]  (tiled smem transpose)
__global__ void tsplit(const float* __restrict__ w, __half* __restrict__ hi,
                       int K, int N)
{
    __shared__ float t[32][33];
    const int k0 = blockIdx.y << 5, n0 = blockIdx.x << 5;
    const int tx = threadIdx.x, ty = threadIdx.y;   // 32 x 8
#pragma unroll
    for (int i = 0; i < 4; i++)
        t[ty + 8 * i][tx] = w[(size_t)(k0 + ty + 8 * i) * N + n0 + tx];
    __syncthreads();
#pragma unroll
    for (int i = 0; i < 4; i++)
        hi[(size_t)(n0 + ty + 8 * i) * K + k0 + tx] = __float2half(t[tx][ty + 8 * i]);
}

// ---------------------------------------------------------------------------
// fp16 GEMM via mma.sync:  C[M,N] = A[M,K] @ B^T[N,K]^T + bias[N]
// BM=256, BN=128, BK=32, 512 threads (16 warps as 4M x 4N, warp tile 64x32).
// 3-stage cp.async ring.  Higher arithmetic intensity (87 FLOP/B from L2)
// flips the kernel from L2-share-bound to compute-bound.
// mode 0: fp32 C store.  mode 1: fused QKV epilogue (RoPE + fp16 scatter).
// ---------------------------------------------------------------------------
#define GST 30720   // A 20480 (256 rows x 80B) | B 10240 (128 rows x 80B)

__global__ __launch_bounds__(512, 1)
void gemm_mma(const __half* __restrict__ Ahp, const __half* __restrict__ Bhp,
              const float* __restrict__ bias, float* __restrict__ C,
              int M, int N, int K, int mode,
              __half* __restrict__ qout, __half* __restrict__ kout,
              __half* __restrict__ vout)
{
    extern __shared__ __align__(16) char smem[];
    const int tid = threadIdx.x, lane = tid & 31, warp = tid >> 5;
    const int wm = warp & 3, wn = warp >> 2;           // 4 x 4 warps
    const int mBase = blockIdx.y * 256, nBase = blockIdx.x * 128;
    u32 sb = (u32)__cvta_generic_to_shared(smem);

    const int g = lane >> 3, rsel = lane & 7;
    const u32 offA = (u32)((wm * 64 + (g & 1) * 8 + rsel) * 80 + (g >> 1) * 16);
    const u32 offB = (u32)((wn * 32 + (g >> 1) * 8 + rsel) * 80 + (g & 1) * 16);

    float acc[4][4][4];
#pragma unroll
    for (int a = 0; a < 4; a++)
#pragma unroll
        for (int b = 0; b < 4; b++)
#pragma unroll
            for (int c = 0; c < 4; c++) acc[a][b][c] = 0.f;

    const int niter = K >> 5;

    auto load_stage = [&](int stage, int kc) {
        u32 st = sb + (u32)stage * GST;
#pragma unroll
        for (int i = 0; i < 3; i++) {
            int ch = i * 512 + tid;              // 0..1535
            int row = ch >> 2, c = ch & 3;       // 384 rows x 4 chunks
            if (row < 256) {
                cpa16(st + (u32)(row * 80 + c * 16),
                      Ahp + (size_t)(mBase + row) * K + kc * 32 + c * 8);
            } else {
                int br = row - 256;
                cpa16(st + 20480 + (u32)(br * 80 + c * 16),
                      Bhp + (size_t)(nBase + br) * K + kc * 32 + c * 8);
            }
        }
        asm volatile("cp.async.commit_group;" ::: "memory");
    };

    load_stage(0, 0);
    load_stage(1, 1);

    for (int it = 0; it < niter; it++) {
        if (it + 1 < niter) {
            asm volatile("cp.async.wait_group 1;" ::: "memory");
        } else {
            asm volatile("cp.async.wait_group 0;" ::: "memory");
        }
        __syncthreads();
        if (it + 2 < niter) load_stage((it + 2) % 3, it + 2);

        u32 st = sb + (u32)(it % 3) * GST;
#pragma unroll
        for (int ks = 0; ks < 2; ks++) {
            u32 ah[4][4], bh[4][2];
#pragma unroll
            for (int mi = 0; mi < 4; mi++)
                ldsm4(ah[mi], st + offA + (u32)(mi * 16 * 80 + ks * 32));
#pragma unroll
            for (int nh = 0; nh < 2; nh++) {
                u32 t[4];
                ldsm4(t, st + 20480 + offB + (u32)(nh * 16 * 80 + ks * 32));
                bh[2 * nh][0] = t[0]; bh[2 * nh][1] = t[1];
                bh[2 * nh + 1][0] = t[2]; bh[2 * nh + 1][1] = t[3];
            }
#pragma unroll
            for (int mi = 0; mi < 4; mi++)
#pragma unroll
                for (int ni = 0; ni < 4; ni++)
                    mma_f16(acc[mi][ni], ah[mi], bh[ni]);
        }
    }

    __syncthreads();
    const int qrow = lane >> 2, t2 = (lane & 3) * 2;

    if (mode == 0) {
#pragma unroll
        for (int mi = 0; mi < 4; mi++) {
            int r0 = mBase + wm * 64 + mi * 16 + qrow;
#pragma unroll
            for (int ni = 0; ni < 4; ni++) {
                int col = nBase + wn * 32 + ni * 8 + t2;
                float b0 = bias[col], b1 = bias[col + 1];
                *(float2*)&C[(size_t)r0 * N + col] =
                    make_float2(acc[mi][ni][0] + b0, acc[mi][ni][1] + b1);
                *(float2*)&C[(size_t)(r0 + 8) * N + col] =
                    make_float2(acc[mi][ni][2] + b0, acc[mi][ni][3] + b1);
            }
        }
    } else {
        // fused QKV epilogue.  N window type within the 384-col head block:
        const int type = (nBase >> 7) % 3;     // 0=q, 1=k, 2=v
        const int h = nBase / 384;
        const bool rot = (wn == 0) && (type < 2);  // cols [0,32) of q/k: RoPE
        float invf[4];
        if (rot) {
            const float cexp = 9.210340371976184f / 16.0f;  // ln(10000)/16
            invf[0] = expf(-(float)(t2)     * cexp);
            invf[1] = expf(-(float)(t2 + 1) * cexp);
            invf[2] = expf(-(float)(t2 + 8) * cexp);
            invf[3] = expf(-(float)(t2 + 9) * cexp);
        }
        __half* outp = (type == 0) ? qout : ((type == 1) ? kout : vout);
        const float sc = (type == 0) ? 0.08838834764831843f : 1.0f;
#pragma unroll
        for (int mi = 0; mi < 4; mi++) {
#pragma unroll
            for (int rr = 0; rr < 2; rr++) {
                int row = mBase + wm * 64 + mi * 16 + qrow + rr * 8;
                int b = row >> 11, s = row & 2047;
                float vals[8];
#pragma unroll
                for (int ni = 0; ni < 4; ni++) {
                    int col = nBase + wn * 32 + ni * 8 + t2;
                    vals[2 * ni]     = acc[mi][ni][2 * rr]     + bias[col];
                    vals[2 * ni + 1] = acc[mi][ni][2 * rr + 1] + bias[col + 1];
                }
                if (rot) {
                    float sn, cs;
#pragma unroll
                    for (int j = 0; j < 2; j++) {
                        sincosf((float)s * invf[j], &sn, &cs);
                        float lo = vals[j], hi = vals[4 + j];
                        vals[j]     = lo * cs - hi * sn;
                        vals[4 + j] = hi * cs + lo * sn;
                        sincosf((float)s * invf[2 + j], &sn, &cs);
                        float lo2 = vals[2 + j], hi2 = vals[6 + j];
                        vals[2 + j] = lo2 * cs - hi2 * sn;
                        vals[6 + j] = hi2 * cs + lo2 * sn;
                    }
                }
                size_t ob = ((size_t)(b * 16 + h) * SEQ + s) * 128 + wn * 32 + t2;
#pragma unroll
                for (int ni = 0; ni < 4; ni++) {
                    __half2 hv = __floats2half2_rn(vals[2 * ni] * sc,
                                                   vals[2 * ni + 1] * sc);
                    *(__half2*)(outp + ob + ni * 8) = hv;
                }
            }
        }
    }
}

// ---------------------------------------------------------------------------
// Flash attention via mma.sync, single fp16, causal, no-max softmax.
// BQ=128 (8 warps x 16 rows), BKV=64 in two 32-col halves, 2 CTAs/SM.
// (Unchanged from R16 — near its smem/issue floor.)
// ---------------------------------------------------------------------------
#define FKV 34816
#define FL_SMEM (34816 + 2 * FKV)

__global__ __launch_bounds__(256, 2)
void flash_mma(const __half* __restrict__ qhp, const __half* __restrict__ khp,
               const __half* __restrict__ vhp, __half* __restrict__ oh)
{
    extern __shared__ __align__(16) char smem[];
    const int tid = threadIdx.x, lane = tid & 31, warp = tid >> 5;
    const int qi = 15 - (int)blockIdx.x;        // heavy q-tiles first
    const int bh = blockIdx.y;
    const int q0 = qi << 7;
    const int nkv = 2 * qi + 2;
    u32 sb = (u32)__cvta_generic_to_shared(smem);

    const int g = lane >> 3, rsel = lane & 7;
    const size_t base = (size_t)bh * SEQ * 128;

    // ---- Q loads (resident @0) ----
#pragma unroll
    for (int i = 0; i < 8; i++) {
        int idx = i * 256 + tid;                 // 0..2047
        int row = idx >> 4, c = idx & 15;
        cpa16(sb + (u32)(row * 272 + c * 16),
              qhp + base + (size_t)(q0 + row) * 128 + c * 8);
    }
    asm volatile("cp.async.commit_group;" ::: "memory");

    auto load_kv = [&](int kt) {
        u32 st = sb + (u32)(34816 + (kt & 1) * FKV);
        const size_t rb = base + (size_t)(kt * 64) * 128;
#pragma unroll
        for (int i = 0; i < 2; i++) {
            int idx = i * 256 + tid;             // 0..511
            int row = idx >> 3, c = idx & 7;     // 64 rows x 8 chunks of 16 cols
            u32 d = st + (u32)(row * 272 + c * 32);
            size_t s = rb + (size_t)row * 128 + c * 16;
            cpa16(d,          khp + s);
            cpa16(d + 16,     khp + s + 8);
            cpa16(d + 17408,      vhp + s);
            cpa16(d + 17408 + 16, vhp + s + 8);
        }
        asm volatile("cp.async.commit_group;" ::: "memory");
    };

    load_kv(0);

    float oacc[16][4];
#pragma unroll
    for (int i = 0; i < 16; i++)
#pragma unroll
        for (int j = 0; j < 4; j++) oacc[i][j] = 0.f;
    float lsum0 = 0.f, lsum1 = 0.f;

    const u32 qoff = sb + (u32)((warp * 16 + (g & 1) * 8 + rsel) * 272 + (g >> 1) * 16);
    const int rowq = warp * 16 + (lane >> 2);        // local q row (of pair)

    for (int kt = 0; kt < nkv; kt++) {
        asm volatile("cp.async.wait_group 0;" ::: "memory");
        __syncthreads();
        if (kt + 1 < nkv) load_kv(kt + 1);
        u32 st = sb + (u32)(34816 + (kt & 1) * FKV);

        const u32 kb = st + (u32)(((g >> 1) * 8 + rsel) * 272 + (g & 1) * 16);
        const u32 vbase = st + 17408 + (u32)(((g & 1) * 8 + rsel) * 272 + (g >> 1) * 16);
        const bool diag = (kt >= 2 * qi);
        const int row0 = q0 + rowq;

        // process this KV tile in two 32-column halves (register diet)
#pragma unroll
        for (int half = 0; half < 2; half++) {
            // ---- S = Q K^T (32 cols) ----
            float sacc[4][4];
#pragma unroll
            for (int i = 0; i < 4; i++)
#pragma unroll
                for (int j = 0; j < 4; j++) sacc[i][j] = 0.f;

            const u32 kbh = kb + (u32)(half * 32 * 272);
#pragma unroll
            for (int ks = 0; ks < 8; ks++) {
                u32 qh4[4];
                ldsm4(qh4, qoff + ks * 32);
                u32 tb0[4], tb1[4];
                ldsm4(tb0, kbh + ks * 32);
                ldsm4(tb1, kbh + 16 * 272 + ks * 32);
                mma_f16(sacc[0], qh4, tb0);
                mma_f16(sacc[1], qh4, tb0 + 2);
                mma_f16(sacc[2], qh4, tb1);
                mma_f16(sacc[3], qh4, tb1 + 2);
            }

            // ---- softmax numerator ----
            const int colb = kt * 64 + half * 32 + 2 * (lane & 3);
            u32 pah[2][4];
#pragma unroll
            for (int ni = 0; ni < 4; ni++) {
                int c0 = colb + ni * 8;
                float p0, p1, p2, p3;
                if (diag) {
                    p0 = (c0     <= row0    ) ? fexp(sacc[ni][0]) : 0.f;
                    p1 = (c0 + 1 <= row0    ) ? fexp(sacc[ni][1]) : 0.f;
                    p2 = (c0     <= row0 + 8) ? fexp(sacc[ni][2]) : 0.f;
                    p3 = (c0 + 1 <= row0 + 8) ? fexp(sacc[ni][3]) : 0.f;
                } else {
                    p0 = fexp(sacc[ni][0]); p1 = fexp(sacc[ni][1]);
                    p2 = fexp(sacc[ni][2]); p3 = fexp(sacc[ni][3]);
                }
                lsum0 += p0 + p1;
                lsum1 += p2 + p3;
                int kt2 = ni >> 1, j = (ni & 1) * 2;
                __half2 h0 = __floats2half2_rn(p0, p1);
                __half2 h1 = __floats2half2_rn(p2, p3);
                pah[kt2][j]     = *(u32*)&h0;
                pah[kt2][j + 1] = *(u32*)&h1;
            }

            // ---- O += P V (32 kv rows) ----
            const u32 vbh = vbase + (u32)(half * 32 * 272);
#pragma unroll
            for (int kt2 = 0; kt2 < 2; kt2++) {
#pragma unroll
                for (int dgp = 0; dgp < 4; dgp++) {
                    u32 th0[4], th1[4];
                    u32 vbb = vbh + kt2 * (16 * 272) + dgp * 64;
                    ldsm4t(th0, vbb);
                    ldsm4t(th1, vbb + 32);
                    mma_f16(oacc[4 * dgp],     pah[kt2], th0);
                    mma_f16(oacc[4 * dgp + 1], pah[kt2], th0 + 2);
                    mma_f16(oacc[4 * dgp + 2], pah[kt2], th1);
                    mma_f16(oacc[4 * dgp + 3], pah[kt2], th1 + 2);
                }
            }
        }
    }

    // ---- normalize + fp16 store into g_ah (out-proj A) ----
    lsum0 += __shfl_xor_sync(0xffffffffu, lsum0, 1);
    lsum0 += __shfl_xor_sync(0xffffffffu, lsum0, 2);
    lsum1 += __shfl_xor_sync(0xffffffffu, lsum1, 1);
    lsum1 += __shfl_xor_sync(0xffffffffu, lsum1, 2);
    float inv0 = 1.f / lsum0, inv1 = 1.f / lsum1;

    const int b = bh >> 4, h = bh & 15;
    const int r0 = q0 + rowq;
    size_t obase0 = ((size_t)(b * SEQ + r0)) * HID + h * 128;
    size_t obase1 = obase0 + (size_t)8 * HID;
#pragma unroll
    for (int dt = 0; dt < 16; dt++) {
        int col = dt * 8 + 2 * (lane & 3);
        __half2 h0 = __floats2half2_rn(oacc[dt][0] * inv0, oacc[dt][1] * inv0);
        __half2 h1 = __floats2half2_rn(oacc[dt][2] * inv1, oacc[dt][3] * inv1);
        *(u32*)(oh + obase0 + col) = *(u32*)&h0;
        *(u32*)(oh + obase1 + col) = *(u32*)&h1;
    }
}

// ---------------------------------------------------------------------------
extern "C" void kernel_launch(void* const* d_in, const int* in_sizes, int n_in,
                              void* d_out, int out_size)
{
    const float* hidden = (const float*)d_in[0];
    const float* qkvk = (const float*)d_in[2];
    const float* qkvb = (const float*)d_in[3];
    const float* outk = (const float*)d_in[4];
    const float* outb = (const float*)d_in[5];
    float* out = (float*)d_out;

    __half *pqh, *pkh, *pvh, *pah, *pbh;
    cudaGetSymbolAddress((void**)&pqh, g_qh);
    cudaGetSymbolAddress((void**)&pkh, g_kh);
    cudaGetSymbolAddress((void**)&pvh, g_vh);
    cudaGetSymbolAddress((void**)&pah, g_ah);
    cudaGetSymbolAddress((void**)&pbh, g_bh);

    cudaFuncSetAttribute((const void*)gemm_mma,
                         cudaFuncAttributeMaxDynamicSharedMemorySize, 3 * GST);
    cudaFuncSetAttribute((const void*)flash_mma,
                         cudaFuncAttributeMaxDynamicSharedMemorySize, FL_SMEM);

    // --- QKV projection + fused RoPE/fp16 epilogue (BM=256) ---
    conv_rm<<<(4096 * 2048 / 4 + 255) / 256, 256>>>((const float4*)hidden, pah, 4096 * 2048 / 4);
    tsplit<<<dim3(6144 / 32, 2048 / 32), dim3(32, 8)>>>(qkvk, pbh, 2048, 6144);
    gemm_mma<<<dim3(48, 16), 512, 3 * GST>>>(pah, pbh, qkvb, nullptr,
                                             4096, 6144, 2048, 1, pqh, pkh, pvh);

    // --- causal flash attention (single-fp16 HMMA, 2 CTAs/SM), writes out-proj A ---
    flash_mma<<<dim3(16, 32), 256, FL_SMEM>>>(pqh, pkh, pvh, pah);

    // --- output projection: [4096,2048] @ [2048,2048] + bias (BM=256) ---
    tsplit<<<dim3(2048 / 32, 2048 / 32), dim3(32, 8)>>>(outk, pbh, 2048, 2048);
    gemm_mma<<<dim3(16, 16), 512, 3 * GST>>>(pah, pbh, outb, out,
                                             4096, 2048, 2048, 0, nullptr, nullptr, nullptr);
}